// round 6
// baseline (speedup 1.0000x reference)
#include <cuda_runtime.h>
#include <cstdint>

#define BB 2
#define NN 4096
#define DD 512
#define HH 8
#define HD 64
#define NH (BB*HH)          // 16
#define MTOT (BB*NN)        // 8192
#define SCALE 0.125f

// Scratch (allocation-free rule: __device__ globals)
__device__ float g_q[NH * NN * HD];     // tf32-rounded, pre-scaled by SCALE
__device__ float g_k[NH * NN * HD];     // tf32-rounded
__device__ float g_v[NH * NN * HD];     // tf32-rounded
__device__ float g_ctx[MTOT * DD];      // tf32-rounded
__device__ float g_xr[MTOT * DD];       // tf32-rounded x
__device__ float g_wqkvr[3 * DD * DD];  // tf32-rounded w_qkv
__device__ float g_wprojr[DD * DD];     // tf32-rounded w_proj

// ---------------------------------------------------------------------------
// primitives
// ---------------------------------------------------------------------------
__device__ __forceinline__ uint32_t f2tf32(float f) {
    uint32_t r;
    asm("cvt.rna.tf32.f32 %0, %1;\n" : "=r"(r) : "f"(f));
    return r;
}
__device__ __forceinline__ float rtf(float f) { return __uint_as_float(f2tf32(f)); }

__device__ __forceinline__ void mma_tf32(float c[4], const uint32_t a[4],
                                         uint32_t b0, uint32_t b1) {
    asm volatile(
        "mma.sync.aligned.m16n8k8.row.col.f32.tf32.tf32.f32 "
        "{%0,%1,%2,%3}, {%4,%5,%6,%7}, {%8,%9}, {%0,%1,%2,%3};\n"
        : "+f"(c[0]), "+f"(c[1]), "+f"(c[2]), "+f"(c[3])
        : "r"(a[0]), "r"(a[1]), "r"(a[2]), "r"(a[3]), "r"(b0), "r"(b1));
}

__device__ __forceinline__ void cp_async16(uint32_t saddr, const void* gptr) {
    asm volatile("cp.async.cg.shared.global [%0], [%1], 16;\n"
                 :: "r"(saddr), "l"(gptr));
}
__device__ __forceinline__ void cp_commit() {
    asm volatile("cp.async.commit_group;\n");
}
__device__ __forceinline__ void cp_wait1() {
    asm volatile("cp.async.wait_group 1;\n");
}
__device__ __forceinline__ void cp_wait0() {
    asm volatile("cp.async.wait_group 0;\n");
}

// ---------------------------------------------------------------------------
// Pre-pass: round fp32 array to tf32 bit patterns (valid fp32 values).
// ---------------------------------------------------------------------------
__global__ void round_tf32_k(const float* __restrict__ in,
                             float* __restrict__ out, int n4) {
    int i = blockIdx.x * blockDim.x + threadIdx.x;
    int stride = gridDim.x * blockDim.x;
    for (; i < n4; i += stride) {
        float4 v = ((const float4*)in)[i];
        v.x = rtf(v.x); v.y = rtf(v.y); v.z = rtf(v.z); v.w = rtf(v.w);
        ((float4*)out)[i] = v;
    }
}

// ---------------------------------------------------------------------------
// tf32 GEMM mainloop, cp.async double-buffered. Inputs are PRE-ROUNDED tf32
// bits, so fragments feed mma directly with no cvt.
// CTA 128x128, k-chunk 32, 8 warps (2x4), warp tile 64x32.
// ---------------------------------------------------------------------------
#define GSTR 36
#define STG_WORDS (128 * GSTR)

__device__ __forceinline__ void tf32_gemm_mainloop(
    const float* __restrict__ A, const float* __restrict__ W,
    int m0, int n0, float acc[4][4][4], float* As, float* Bs)
{
    const int tid  = threadIdx.x;
    const int lane = tid & 31;
    const int w    = tid >> 5;
    const int g    = lane >> 2;
    const int t    = lane & 3;
    const int wm   = (w & 1) * 64;
    const int wn   = (w >> 1) * 32;

    const int lrow = tid >> 1;
    const int lcb  = (tid & 1) * 16;

    const float* aptr = A + (size_t)(m0 + lrow) * DD + lcb;
    const float* bptr = W + (size_t)(n0 + lrow) * DD + lcb;
    const uint32_t sa = (uint32_t)__cvta_generic_to_shared(As + lrow * GSTR + lcb);
    const uint32_t sb = (uint32_t)__cvta_generic_to_shared(Bs + lrow * GSTR + lcb);

#pragma unroll
    for (int mi = 0; mi < 4; mi++)
#pragma unroll
        for (int ni = 0; ni < 4; ni++)
#pragma unroll
            for (int r = 0; r < 4; r++) acc[mi][ni][r] = 0.f;

    const int nchunks = DD / 32;   // 16

#pragma unroll
    for (int i = 0; i < 4; i++) {
        cp_async16(sa + (4 * i) * 4, aptr + 4 * i);
        cp_async16(sb + (4 * i) * 4, bptr + 4 * i);
    }
    cp_commit();

    for (int kc = 0; kc < nchunks; kc++) {
        const int cur = kc & 1;
        if (kc + 1 < nchunks) {
            const int nxt = 1 - cur;
            const float* an = aptr + (kc + 1) * 32;
            const float* bn = bptr + (kc + 1) * 32;
#pragma unroll
            for (int i = 0; i < 4; i++) {
                cp_async16(sa + (nxt * STG_WORDS + 4 * i) * 4, an + 4 * i);
                cp_async16(sb + (nxt * STG_WORDS + 4 * i) * 4, bn + 4 * i);
            }
            cp_commit();
            cp_wait1();
        } else {
            cp_wait0();
        }
        __syncthreads();

        const float* Ac = As + cur * STG_WORDS;
        const float* Bc = Bs + cur * STG_WORDS;
#pragma unroll
        for (int ks = 0; ks < 4; ks++) {
            uint32_t af[4][4];
#pragma unroll
            for (int mi = 0; mi < 4; mi++) {
                int mrow = wm + mi * 16 + g;
                af[mi][0] = __float_as_uint(Ac[mrow * GSTR + ks * 8 + t]);
                af[mi][1] = __float_as_uint(Ac[(mrow + 8) * GSTR + ks * 8 + t]);
                af[mi][2] = __float_as_uint(Ac[mrow * GSTR + ks * 8 + t + 4]);
                af[mi][3] = __float_as_uint(Ac[(mrow + 8) * GSTR + ks * 8 + t + 4]);
            }
#pragma unroll
            for (int ni = 0; ni < 4; ni++) {
                int nrow = wn + ni * 8 + g;
                uint32_t b0 = __float_as_uint(Bc[nrow * GSTR + ks * 8 + t]);
                uint32_t b1 = __float_as_uint(Bc[nrow * GSTR + ks * 8 + t + 4]);
#pragma unroll
                for (int mi = 0; mi < 4; mi++)
                    mma_tf32(acc[mi][ni], af[mi], b0, b1);
            }
        }
        __syncthreads();
    }
}

#define GEMM_SMEM (4 * STG_WORDS * 4)   // 73728 B

// ---------------------------------------------------------------------------
// Kernel 1: QKV GEMM. Scatter epilogue writes tf32-rounded q*SCALE / k / v.
// ---------------------------------------------------------------------------
__global__ __launch_bounds__(256, 2) void qkv_gemm_mma(
    const float* __restrict__ x, const float* __restrict__ wqkv)
{
    extern __shared__ float sm[];
    float* As = sm;
    float* Bs = sm + 2 * STG_WORDS;

    const int m0 = blockIdx.y * 128;
    const int n0 = blockIdx.x * 128;
    float acc[4][4][4];
    tf32_gemm_mainloop(x, wqkv, m0, n0, acc, As, Bs);

    const int lane = threadIdx.x & 31;
    const int w    = threadIdx.x >> 5;
    const int g    = lane >> 2;
    const int t    = lane & 3;
    const int wm   = (w & 1) * 64;
    const int wn   = (w >> 1) * 32;

#pragma unroll
    for (int mi = 0; mi < 4; mi++) {
#pragma unroll
        for (int half = 0; half < 2; half++) {
            int m = m0 + wm + mi * 16 + g + half * 8;
            int b = m >> 12;
            int seq = m & (NN - 1);
#pragma unroll
            for (int ni = 0; ni < 4; ni++) {
                int n = n0 + wn + ni * 8 + 2 * t;
                int three = n >> 9;
                int h = (n >> 6) & 7;
                int hd = n & 63;
                float* dst = (three == 0) ? g_q : (three == 1) ? g_k : g_v;
                float v0 = half ? acc[mi][ni][2] : acc[mi][ni][0];
                float v1 = half ? acc[mi][ni][3] : acc[mi][ni][1];
                if (three == 0) { v0 *= SCALE; v1 *= SCALE; }
                float2 val = make_float2(rtf(v0), rtf(v1));
                *(float2*)&dst[((size_t)(b * HH + h) * NN + seq) * HD + hd] = val;
            }
        }
    }
}

// ---------------------------------------------------------------------------
// Kernel 3: output projection + bias (inputs pre-rounded).
// ---------------------------------------------------------------------------
__global__ __launch_bounds__(256, 2) void proj_gemm_mma(
    const float* __restrict__ wproj, const float* __restrict__ bias,
    float* __restrict__ out)
{
    extern __shared__ float sm[];
    float* As = sm;
    float* Bs = sm + 2 * STG_WORDS;

    const int m0 = blockIdx.y * 128;
    const int n0 = blockIdx.x * 128;
    float acc[4][4][4];
    tf32_gemm_mainloop(g_ctx, wproj, m0, n0, acc, As, Bs);

    const int lane = threadIdx.x & 31;
    const int w    = threadIdx.x >> 5;
    const int g    = lane >> 2;
    const int t    = lane & 3;
    const int wm   = (w & 1) * 64;
    const int wn   = (w >> 1) * 32;

#pragma unroll
    for (int mi = 0; mi < 4; mi++) {
#pragma unroll
        for (int ni = 0; ni < 4; ni++) {
            int n = n0 + wn + ni * 8 + 2 * t;
            float bx = bias[n], by = bias[n + 1];
            int m = m0 + wm + mi * 16 + g;
            *(float2*)&out[(size_t)m * DD + n] =
                make_float2(acc[mi][ni][0] + bx, acc[mi][ni][1] + by);
            *(float2*)&out[(size_t)(m + 8) * DD + n] =
                make_float2(acc[mi][ni][2] + bx, acc[mi][ni][3] + by);
        }
    }
}

// ---------------------------------------------------------------------------
// Kernel 2: flash attention, tf32 mma, cp.async double-buffered K/V.
// g_q pre-scaled+rounded; g_k/g_v pre-rounded -> zero cvt in the hot loop.
// Ks [kv][d] stride 68, Vs stride 72 (both conflict-free for frag loads).
// ---------------------------------------------------------------------------
#define KT 64
#define QT 128
#define KSTR 68
#define VSTR 72
#define KT_WORDS (KT * KSTR)   // 4352
#define VT_WORDS (KT * VSTR)   // 4608
#define ATTN_SMEM ((2 * KT_WORDS + 2 * VT_WORDS) * 4)   // 71680 B

__global__ __launch_bounds__(256, 2) void attn_mma() {
    extern __shared__ float sm[];
    float* Kbuf = sm;                    // [2][KT_WORDS]
    float* Vbuf = sm + 2 * KT_WORDS;     // [2][VT_WORDS]

    const int tid  = threadIdx.x;
    const int lane = tid & 31;
    const int w    = tid >> 5;
    const int g    = lane >> 2;
    const int t    = lane & 3;

    const int bh = blockIdx.y;
    const int qt = blockIdx.x;

    const float* qbase = g_q + (size_t)(bh * NN + qt * QT + w * 16) * HD;
    const float* kbase = g_k + (size_t)bh * NN * HD;
    const float* vbase = g_v + (size_t)bh * NN * HD;

    // per-thread producer addresses (4 chunks K + 4 chunks V per tile)
    uint32_t ks_s[4], vs_s[4];
    int koff_g[4];
#pragma unroll
    for (int it = 0; it < 4; it++) {
        int idx = tid + 256 * it;
        int r = idx >> 4;
        int c4 = idx & 15;
        ks_s[it] = (uint32_t)__cvta_generic_to_shared(Kbuf + r * KSTR + c4 * 4);
        vs_s[it] = (uint32_t)__cvta_generic_to_shared(Vbuf + r * VSTR + c4 * 4);
        koff_g[it] = r * HD + c4 * 4;
    }

    // Q fragments: direct bit loads (pre-rounded, pre-scaled)
    uint32_t qf[8][4];
#pragma unroll
    for (int j = 0; j < 8; j++) {
        qf[j][0] = __float_as_uint(qbase[g       * HD + 8 * j + t]);
        qf[j][1] = __float_as_uint(qbase[(g + 8) * HD + 8 * j + t]);
        qf[j][2] = __float_as_uint(qbase[g       * HD + 8 * j + t + 4]);
        qf[j][3] = __float_as_uint(qbase[(g + 8) * HD + 8 * j + t + 4]);
    }

    float o[8][4];
#pragma unroll
    for (int n = 0; n < 8; n++)
#pragma unroll
        for (int i = 0; i < 4; i++) o[n][i] = 0.f;
    float mo0 = -1e30f, mo1 = -1e30f;
    float l0 = 0.f, l1 = 0.f;

    // prefetch tile 0 into stage 0
#pragma unroll
    for (int it = 0; it < 4; it++) {
        cp_async16(ks_s[it], kbase + koff_g[it]);
        cp_async16(vs_s[it], vbase + koff_g[it]);
    }
    cp_commit();

    const int ntiles = NN / KT;   // 64
    for (int ktile = 0; ktile < ntiles; ktile++) {
        const int cur = ktile & 1;
        if (ktile + 1 < ntiles) {
            const int nxt = 1 - cur;
            const float* kn = kbase + (size_t)(ktile + 1) * KT * HD;
            const float* vn = vbase + (size_t)(ktile + 1) * KT * HD;
#pragma unroll
            for (int it = 0; it < 4; it++) {
                cp_async16(ks_s[it] + nxt * KT_WORDS * 4, kn + koff_g[it]);
                cp_async16(vs_s[it] + nxt * VT_WORDS * 4, vn + koff_g[it]);
            }
            cp_commit();
            cp_wait1();
        } else {
            cp_wait0();
        }
        __syncthreads();

        const float* Kc = Kbuf + cur * KT_WORDS;
        const float* Vc = Vbuf + cur * VT_WORDS;

        // S = Q K^T
        float s[8][4];
#pragma unroll
        for (int n = 0; n < 8; n++)
#pragma unroll
            for (int i = 0; i < 4; i++) s[n][i] = 0.f;

#pragma unroll
        for (int j = 0; j < 8; j++) {
#pragma unroll
            for (int n = 0; n < 8; n++) {
                uint32_t b0 = __float_as_uint(Kc[(n * 8 + g) * KSTR + 8 * j + t]);
                uint32_t b1 = __float_as_uint(Kc[(n * 8 + g) * KSTR + 8 * j + t + 4]);
                mma_tf32(s[n], qf[j], b0, b1);
            }
        }

        // online softmax in registers
        float mx0 = -1e30f, mx1 = -1e30f;
#pragma unroll
        for (int n = 0; n < 8; n++) {
            mx0 = fmaxf(mx0, fmaxf(s[n][0], s[n][1]));
            mx1 = fmaxf(mx1, fmaxf(s[n][2], s[n][3]));
        }
        mx0 = fmaxf(mx0, __shfl_xor_sync(0xffffffffu, mx0, 1));
        mx0 = fmaxf(mx0, __shfl_xor_sync(0xffffffffu, mx0, 2));
        mx1 = fmaxf(mx1, __shfl_xor_sync(0xffffffffu, mx1, 1));
        mx1 = fmaxf(mx1, __shfl_xor_sync(0xffffffffu, mx1, 2));

        float mn0 = fmaxf(mo0, mx0);
        float mn1 = fmaxf(mo1, mx1);
        float corr0 = __expf(mo0 - mn0);
        float corr1 = __expf(mo1 - mn1);
        float rs0 = 0.f, rs1 = 0.f;
#pragma unroll
        for (int n = 0; n < 8; n++) {
            s[n][0] = __expf(s[n][0] - mn0);
            s[n][1] = __expf(s[n][1] - mn0);
            s[n][2] = __expf(s[n][2] - mn1);
            s[n][3] = __expf(s[n][3] - mn1);
            rs0 += s[n][0] + s[n][1];
            rs1 += s[n][2] + s[n][3];
        }
        rs0 += __shfl_xor_sync(0xffffffffu, rs0, 1);
        rs0 += __shfl_xor_sync(0xffffffffu, rs0, 2);
        rs1 += __shfl_xor_sync(0xffffffffu, rs1, 1);
        rs1 += __shfl_xor_sync(0xffffffffu, rs1, 2);
        l0 = l0 * corr0 + rs0;
        l1 = l1 * corr1 + rs1;
        mo0 = mn0; mo1 = mn1;
#pragma unroll
        for (int n = 0; n < 8; n++) {
            o[n][0] *= corr0; o[n][1] *= corr0;
            o[n][2] *= corr1; o[n][3] *= corr1;
        }

        // O += P V : C-frag -> A-frag via intra-quad shuffles
        const int srcA = (lane & 28) | (t >> 1);
        const int srcB = srcA + 2;
        const bool odd = (t & 1);
#pragma unroll
        for (int j = 0; j < 8; j++) {
            float s0 = __shfl_sync(0xffffffffu, s[j][0], srcA);
            float s1 = __shfl_sync(0xffffffffu, s[j][1], srcA);
            float s2 = __shfl_sync(0xffffffffu, s[j][2], srcA);
            float s3 = __shfl_sync(0xffffffffu, s[j][3], srcA);
            float u0 = __shfl_sync(0xffffffffu, s[j][0], srcB);
            float u1 = __shfl_sync(0xffffffffu, s[j][1], srcB);
            float u2 = __shfl_sync(0xffffffffu, s[j][2], srcB);
            float u3 = __shfl_sync(0xffffffffu, s[j][3], srcB);
            uint32_t a[4];
            a[0] = f2tf32(odd ? s1 : s0);
            a[1] = f2tf32(odd ? s3 : s2);
            a[2] = f2tf32(odd ? u1 : u0);
            a[3] = f2tf32(odd ? u3 : u2);
#pragma unroll
            for (int n = 0; n < 8; n++) {
                uint32_t b0 = __float_as_uint(Vc[(8 * j + t) * VSTR + 8 * n + g]);
                uint32_t b1 = __float_as_uint(Vc[(8 * j + t + 4) * VSTR + 8 * n + g]);
                mma_tf32(o[n], a, b0, b1);
            }
        }
        __syncthreads();   // all reads of stage done before reissue
    }

    // epilogue: write tf32-rounded ctx (proj consumes bits directly)
    const int b = bh >> 3;
    const int h = bh & 7;
    const int seq0 = qt * QT + w * 16 + g;
    const float inv0 = 1.f / l0;
    const float inv1 = 1.f / l1;
#pragma unroll
    for (int n = 0; n < 8; n++) {
        int col = h * HD + 8 * n + 2 * t;
        float2 r0 = make_float2(rtf(o[n][0] * inv0), rtf(o[n][1] * inv0));
        float2 r1 = make_float2(rtf(o[n][2] * inv1), rtf(o[n][3] * inv1));
        *(float2*)&g_ctx[(size_t)(b * NN + seq0) * DD + col] = r0;
        *(float2*)&g_ctx[(size_t)(b * NN + seq0 + 8) * DD + col] = r1;
    }
}

// ---------------------------------------------------------------------------

extern "C" void kernel_launch(void* const* d_in, const int* in_sizes, int n_in,
                              void* d_out, int out_size) {
    const float* x      = (const float*)d_in[0];
    const float* w_qkv  = (const float*)d_in[1];
    const float* w_proj = (const float*)d_in[2];
    const float* b_proj = (const float*)d_in[3];
    float* out = (float*)d_out;

    static int cfg_done = 0;
    if (!cfg_done) {
        cudaFuncSetAttribute(qkv_gemm_mma,
                             cudaFuncAttributeMaxDynamicSharedMemorySize, GEMM_SMEM);
        cudaFuncSetAttribute(proj_gemm_mma,
                             cudaFuncAttributeMaxDynamicSharedMemorySize, GEMM_SMEM);
        cudaFuncSetAttribute(attn_mma,
                             cudaFuncAttributeMaxDynamicSharedMemorySize, ATTN_SMEM);
        cfg_done = 1;
    }

    // pre-round inputs to tf32 bit patterns
    round_tf32_k<<<256, 256>>>(x, g_xr, MTOT * DD / 4);
    round_tf32_k<<<64, 256>>>(w_qkv, g_wqkvr, 3 * DD * DD / 4);
    round_tf32_k<<<32, 256>>>(w_proj, g_wprojr, DD * DD / 4);

    qkv_gemm_mma<<<dim3(1536 / 128, MTOT / 128), 256, GEMM_SMEM>>>(g_xr, g_wqkvr);
    attn_mma<<<dim3(NN / QT, NH), 256, ATTN_SMEM>>>();
    proj_gemm_mma<<<dim3(DD / 128, MTOT / 128), 256, GEMM_SMEM>>>(g_wprojr, b_proj, out);
}